// round 15
// baseline (speedup 1.0000x reference)
#include <cuda_runtime.h>
#include <math.h>

#define BB 128
#define SS 128
#define WW 16
#define CEd 64
#define HHd 256
#define KK 27
#define NSTART 25
#define NSTOP 26
#define NW (BB*SS)
#define CV 500

typedef unsigned long long u64;

__device__ __forceinline__ u64 pack2(float a, float b){ u64 r; asm("mov.b64 %0,{%1,%2};":"=l"(r):"f"(a),"f"(b)); return r; }
__device__ __forceinline__ float2 unpack2(u64 v){ float2 f; asm("mov.b64 {%0,%1},%2;":"=f"(f.x),"=f"(f.y):"l"(v)); return f; }
__device__ __forceinline__ u64 ffma2(u64 a, u64 b, u64 c){ u64 d; asm("fma.rn.f32x2 %0,%1,%2,%3;":"=l"(d):"l"(a),"l"(b),"l"(c)); return d; }
__device__ __forceinline__ u64 add2(u64 a, u64 b){ u64 d; asm("add.rn.f32x2 %0,%1,%2;":"=l"(d):"l"(a),"l"(b)); return d; }

__device__ __forceinline__ float sigf(float x){ return 1.0f/(1.0f+__expf(-x)); }
__device__ __forceinline__ float tanhfast(float x){ return 2.0f/(1.0f+__expf(-2.0f*x)) - 1.0f; }

// ---------------- static scratch ----------------
__device__ float g_coWT[128*64];
__device__ float g_cWT[2*64*256];
__device__ float g_cproj[2*CV*256];
__device__ float g_hf[NW*CEd];
__device__ float g_hb[NW*CEd];
__device__ float g_chvec[NW*CEd];
__device__ float g_fv[NW*128];
__device__ float g_vec192[NW*192];
__device__ float g_W4[2*1024*4];
__device__ float g_bias2[2*1024];
__device__ float g_gx[2*SS*BB*1024];
__device__ float g_hT[2*2*8*8*512];            // [buf][dir][sg][us][32u][16s]
__device__ float g_hout[NW*512];
__device__ float g_feats[NW*KK];
__device__ volatile unsigned g_flag[16*8*8];   // [grp][us] stride 8, monotonic

// ---------------- tiny transposes ----------------
__global__ void prep_transpose_kernel(const float* __restrict__ coW,
    const float* __restrict__ cWf, const float* __restrict__ cWb)
{
    int i = blockIdx.x*256 + threadIdx.x;
    if (i < 64*128) {
        int m = i >> 7, j = i & 127;
        g_coWT[j*64 + m] = coW[i];
    }
    if (i < 256*64) {
        int t = i >> 6, j = i & 63;
        g_cWT[0*16384 + j*256 + t] = cWf[i];
        g_cWT[1*16384 + j*256 + t] = cWb[i];
    }
}

// ---------------- fold char_emb @ Wih^T + bias into vocab table ----------------
__global__ void ce_proj_kernel(const float* __restrict__ ce,
    const float* __restrict__ bihf, const float* __restrict__ bhhf,
    const float* __restrict__ bihb, const float* __restrict__ bhhb)
{
    int v = blockIdx.x, dir = blockIdx.y, t = threadIdx.x;
    __shared__ float e[64];
    if (t < 64) e[t] = ce[v*64 + t];
    __syncthreads();
    const float* WT = g_cWT + dir*16384;
    float acc = dir ? (bihb[t] + bhhb[t]) : (bihf[t] + bhhf[t]);
    #pragma unroll
    for (int j = 0; j < 64; j++) acc += WT[j*256 + t]*e[j];
    g_cproj[(dir*CV + v)*256 + t] = acc;
}

// ---------------- fold Wih_fv @ featW (rank-4) + bias ----------------
__global__ void w4_kernel(const float* __restrict__ Wf, const float* __restrict__ Wb,
    const float* __restrict__ featW, const float* __restrict__ featb,
    const float* __restrict__ bihf, const float* __restrict__ bhhf,
    const float* __restrict__ bihb, const float* __restrict__ bhhb)
{
    int r = blockIdx.x*256 + threadIdx.x;
    int dir = blockIdx.y;
    const float* W = dir ? Wb : Wf;
    float a0=0.f,a1=0.f,a2=0.f,a3=0.f,ab=0.f;
    #pragma unroll 4
    for (int m = 0; m < 128; m++) {
        float w = W[r*320 + 192 + m];
        a0 += w*featW[m*4+0]; a1 += w*featW[m*4+1];
        a2 += w*featW[m*4+2]; a3 += w*featW[m*4+3];
        ab += w*featb[m];
    }
    g_W4[(dir*1024+r)*4+0]=a0; g_W4[(dir*1024+r)*4+1]=a1;
    g_W4[(dir*1024+r)*4+2]=a2; g_W4[(dir*1024+r)*4+3]=a3;
    g_bias2[dir*1024+r] = (dir ? bihb[r]+bhhb[r] : bihf[r]+bhhf[r]) + ab;
}

// ---------------- char BiLSTM: two-group software pipeline ----------------
__global__ __launch_bounds__(256,2) void char_lstm_kernel(
    const int* __restrict__ chars2ix,
    const float* __restrict__ Whh_f, const float* __restrict__ Whh_b)
{
    int t = threadIdx.x;
    int dir = blockIdx.y;
    const float* Whh = dir ? Whh_b : Whh_f;
    float* hout = dir ? g_hb : g_hf;
    const float* tab = g_cproj + dir*CV*256;

    u64 whp[32];
    #pragma unroll
    for (int j = 0; j < 32; j++) whp[j] = *(const u64*)&Whh[t*64 + 2*j];

    __shared__ __align__(16) float hs[2][8*68];
    __shared__ float cs[2][512];
    __shared__ float gs[2][256*9];
    __shared__ int cix[256];

    for (int q = blockIdx.x; q < NW/16; q += gridDim.x) {
        int w0 = q*16;
        cix[t] = chars2ix[w0*WW + t];
        for (int i = t; i < 1088; i += 256) ((float*)hs)[i] = 0.f;
        cs[0][t] = 0.f; cs[0][t+256] = 0.f;
        cs[1][t] = 0.f; cs[1][t+256] = 0.f;
        __syncthreads();

        #pragma unroll 1
        for (int p = 0; p <= 32; p++) {
            if (p >= 1) {
                int gu = (p-1) & 1;
                #pragma unroll
                for (int rep = 0; rep < 2; rep++) {
                    int idx = t + rep*256;
                    int u = idx >> 3, w = idx & 7;
                    float gi = gs[gu][u*9 + w];
                    float gf = gs[gu][(64+u)*9 + w];
                    float gg = gs[gu][(128+u)*9 + w];
                    float go = gs[gu][(192+u)*9 + w];
                    float c = sigf(gf)*cs[gu][idx] + sigf(gi)*tanhfast(gg);
                    cs[gu][idx] = c;
                    hs[gu][w*68 + u] = sigf(go)*tanhfast(c);
                }
            }
            if (p < 32) {
                int gm = p & 1, sm = p >> 1;
                int st = dir ? (WW-1-sm) : sm;
                float gxv[8];
                #pragma unroll
                for (int w = 0; w < 8; w++)
                    gxv[w] = tab[cix[(gm*8 + w)*16 + st]*256 + t];
                u64 acc[8];
                #pragma unroll
                for (int w = 0; w < 8; w++) acc[w] = 0ull;
                #pragma unroll
                for (int j4 = 0; j4 < 16; j4++) {
                    #pragma unroll
                    for (int w = 0; w < 8; w++) {
                        ulonglong2 hv = *(const ulonglong2*)&hs[gm][w*68 + j4*4];
                        acc[w] = ffma2(whp[2*j4],   hv.x, acc[w]);
                        acc[w] = ffma2(whp[2*j4+1], hv.y, acc[w]);
                    }
                }
                #pragma unroll
                for (int w = 0; w < 8; w++) {
                    float2 f = unpack2(acc[w]);
                    gs[gm][t*9 + w] = f.x + f.y + gxv[w];
                }
            }
            __syncthreads();
        }
        #pragma unroll
        for (int rep = 0; rep < 4; rep++) {
            int idx = t + rep*256;
            int u = idx & 63, wl = idx >> 6;
            hout[(w0 + wl)*CEd + u] = hs[wl >> 3][(wl & 7)*68 + u];
        }
        __syncthreads();
    }
}

// ---------------- chvec ----------------
__global__ __launch_bounds__(256) void chvec_kernel(const float* __restrict__ cob)
{
    for (int i = blockIdx.x*blockDim.x + threadIdx.x; i < NW*CEd; i += gridDim.x*blockDim.x) {
        int w = i >> 6, m = i & 63;
        float acc = cob[m];
        const float* hf = g_hf + w*CEd;
        const float* hb = g_hb + w*CEd;
        #pragma unroll 8
        for (int j = 0; j < 64; j++) acc += g_coWT[j*64 + m]*hf[j];
        #pragma unroll 8
        for (int j = 0; j < 64; j++) acc += g_coWT[(64+j)*64 + m]*hb[j];
        g_chvec[i] = acc;
    }
}

// ---------------- fv + assemble vec192 ----------------
__global__ void fv_vec_kernel(const float* __restrict__ features,
                              const float* __restrict__ featW, const float* __restrict__ featb,
                              const int* __restrict__ words2ix, const float* __restrict__ word_emb)
{
    for (int idx = blockIdx.x*blockDim.x + threadIdx.x; idx < NW*320; idx += gridDim.x*blockDim.x) {
        int w = idx / 320;
        int j = idx - w*320;
        if (j < 128) {
            g_vec192[w*192 + j] = word_emb[ words2ix[w]*128 + j ];
        } else if (j < 192) {
            g_vec192[w*192 + j] = g_chvec[w*64 + (j-128)];
        } else {
            int m = j - 192;
            int b = w >> 7, s = w & 127;
            float v = featb[m];
            #pragma unroll
            for (int f = 0; f < 4; f++) v += featW[m*4+f]*features[(b*4+f)*SS + s];
            g_fv[w*128 + m] = v;
        }
    }
}

// ---------------- input GEMM (K=192), register-prefetch pipelined ----------------
__global__ __launch_bounds__(256,2) void gx_gemm_kernel(
    const float* __restrict__ Wf, const float* __restrict__ Wb,
    const float* __restrict__ features)
{
    int ntile = blockIdx.x, mtile = blockIdx.y;
    int dir = ntile >> 3;
    const float* W = dir ? Wb : Wf;
    int n0 = (ntile & 7) * 128, m0 = mtile * 128;

    __shared__ float As[8][132];
    __shared__ float Bs[8][132];

    int tid = threadIdx.x;
    int lrow = tid >> 1, lk = (tid & 1) * 4;
    int m = m0 + lrow, tt = m >> 7, sq = m & 127;
    const float* arow = g_vec192 + (sq*SS + tt)*192;
    const float* brow = W + (n0 + lrow)*320;
    int tm = tid >> 4, tn = tid & 15;

    u64 acc[8][4];
    #pragma unroll
    for (int i=0;i<8;i++){ acc[i][0]=0ull; acc[i][1]=0ull; acc[i][2]=0ull; acc[i][3]=0ull; }

    float4 av = *(const float4*)(arow + lk);
    float4 bv = *(const float4*)(brow + lk);

    for (int kb = 0; kb < 192; kb += 8) {
        __syncthreads();
        As[lk+0][lrow]=av.x; As[lk+1][lrow]=av.y; As[lk+2][lrow]=av.z; As[lk+3][lrow]=av.w;
        Bs[lk+0][lrow]=bv.x; Bs[lk+1][lrow]=bv.y; Bs[lk+2][lrow]=bv.z; Bs[lk+3][lrow]=bv.w;
        if (kb + 8 < 192) {
            av = *(const float4*)(arow + kb + 8 + lk);
            bv = *(const float4*)(brow + kb + 8 + lk);
        }
        __syncthreads();
        #pragma unroll
        for (int k=0;k<8;k++){
            float af[8];
            *(float4*)(af)   = *(const float4*)&As[k][tm*8];
            *(float4*)(af+4) = *(const float4*)&As[k][tm*8+4];
            ulonglong2 b0 = *(const ulonglong2*)&Bs[k][tn*8];
            ulonglong2 b1 = *(const ulonglong2*)&Bs[k][tn*8+4];
            #pragma unroll
            for (int i=0;i<8;i++){
                u64 ap = pack2(af[i], af[i]);
                acc[i][0]=ffma2(ap,b0.x,acc[i][0]);
                acc[i][1]=ffma2(ap,b0.y,acc[i][1]);
                acc[i][2]=ffma2(ap,b1.x,acc[i][2]);
                acc[i][3]=ffma2(ap,b1.y,acc[i][3]);
            }
        }
    }
    float w4v[8][4], bv2[8];
    #pragma unroll
    for (int j=0;j<8;j++){
        int r = n0 + tn*8 + j;
        *(float4*)&w4v[j][0] = *(const float4*)&g_W4[(dir*1024+r)*4];
        bv2[j] = g_bias2[dir*1024+r];
    }
    #pragma unroll
    for (int i=0;i<8;i++){
        int mm = m0 + tm*8 + i;
        int tq = mm >> 7, s = mm & 127;
        float f0 = features[(s*4+0)*SS + tq];
        float f1 = features[(s*4+1)*SS + tq];
        float f2 = features[(s*4+2)*SS + tq];
        float f3 = features[(s*4+3)*SS + tq];
        float* dst = g_gx + ((dir*SS + tq)*BB + s)*1024 + n0 + tn*8;
        float o[8];
        #pragma unroll
        for (int j2=0;j2<4;j2++){
            float2 f = unpack2(acc[i][j2]);
            o[2*j2]   = f.x;
            o[2*j2+1] = f.y;
        }
        #pragma unroll
        for (int j=0;j<8;j++)
            o[j] += bv2[j] + f0*w4v[j][0] + f1*w4v[j][1] + f2*w4v[j][2] + f3*w4v[j][3];
        *(float4*)(dst)   = *(float4*)(o);
        *(float4*)(dst+4) = *(float4*)(o+4);
    }
}

// ---------------- persistent recurrent BiLSTM: dataflow flags + leader fence + own-chunk fast path ----------------
__global__ __launch_bounds__(512,1) void lstm_persist_kernel(
    const float* __restrict__ Whh_f, const float* __restrict__ Whh_b)
{
    int bx = blockIdx.x, tid = threadIdx.x;
    int dir = bx >> 6, us = (bx >> 3) & 7, sg = bx & 7, sbase = sg*16;
    int grp = dir*8 + sg;
    const float* Whh = dir ? Whh_b : Whh_f;

    const int kq = tid >> 7;
    const int r  = tid & 127;
    const int tg = tid & 127;
    const int uul = tid & 31, sq5 = tid >> 5;
    const int uu = us*32 + uul;

    float w[64];
    {
        int g = r >> 5, u = us*32 + (r & 31);
        #pragma unroll
        for (int k = 0; k < 64; k++) w[k] = Whh[(g*HHd + u)*HHd + kq*64 + k];
    }

    __shared__ __align__(16) float xh[4096];
    __shared__ float gsm[4*128*18];

    float* hT_grp0 = g_hT + ((0*2 + dir)*8 + sg)*4096;
    float* hT_grp1 = g_hT + ((1*2 + dir)*8 + sg)*4096;
    volatile unsigned* myflag = &g_flag[(grp*8 + us)*8];
    const unsigned F0 = *myflag;

    float c = 0.f;

    #pragma unroll 1
    for (int ts = 0; ts < SS; ts++) {
        int tx = dir ? (SS-1-ts) : ts;
        float gxv0, gxv1, gxv2, gxv3;
        {
            const float* gp = g_gx + ((dir*SS + tx)*BB + sbase + sq5)*1024 + uu;
            gxv0 = __ldcg(gp);
            gxv1 = __ldcg(gp + 256);
            gxv2 = __ldcg(gp + 512);
            gxv3 = __ldcg(gp + 768);
        }
        u64 acc[8];
        #pragma unroll
        for (int j = 0; j < 8; j++) acc[j] = 0ull;
        #pragma unroll
        for (int half = 0; half < 2; half++) {
            int ch = 2*kq + half;
            bool own_fast = (ch == us) && (ts > 0);   // group-uniform
            if (!own_fast) {
                if (ts > 0) {
                    volatile unsigned* fl = &g_flag[(grp*8 + ch)*8];
                    unsigned tgt = F0 + (unsigned)ts;
                    while (*fl < tgt) { }
                }
                {
                    float4 hv;
                    if (ts == 0) hv = make_float4(0.f,0.f,0.f,0.f);
                    else {
                        const float* src = (((ts & 1) ? hT_grp1 : hT_grp0)) + ch*512 + tg*4;
                        hv = __ldcg((const float4*)src);
                    }
                    *(float4*)&xh[ch*512 + tg*4] = hv;
                }
                asm volatile("bar.sync %0, %1;" :: "r"(kq+1), "r"(128) : "memory");
            }
            const float* xb = xh + ch*512;
            int woff = half*32;
            #pragma unroll
            for (int k = 0; k < 32; k++) {
                u64 wp = pack2(w[woff+k], w[woff+k]);
                const float* xr = xb + k*16;
                ulonglong2 x0 = *(const ulonglong2*)(xr);
                ulonglong2 x1 = *(const ulonglong2*)(xr+4);
                acc[0]=ffma2(wp,x0.x,acc[0]); acc[1]=ffma2(wp,x0.y,acc[1]);
                acc[2]=ffma2(wp,x1.x,acc[2]); acc[3]=ffma2(wp,x1.y,acc[3]);
                ulonglong2 x2 = *(const ulonglong2*)(xr+8);
                ulonglong2 x3 = *(const ulonglong2*)(xr+12);
                acc[4]=ffma2(wp,x2.x,acc[4]); acc[5]=ffma2(wp,x2.y,acc[5]);
                acc[6]=ffma2(wp,x3.x,acc[6]); acc[7]=ffma2(wp,x3.y,acc[7]);
            }
        }
        {
            float* gp = &gsm[(kq*128 + r)*18];
            #pragma unroll
            for (int j = 0; j < 8; j++) *(u64*)&gp[2*j] = acc[j];
        }
        __syncthreads();
        float h;
        {
            float gi = gxv0, gf = gxv1, gg = gxv2, go = gxv3;
            #pragma unroll
            for (int q = 0; q < 4; q++) {
                const float* gp = &gsm[q*128*18 + sq5];
                gi += gp[(uul)*18];
                gf += gp[(32+uul)*18];
                gg += gp[(64+uul)*18];
                go += gp[(96+uul)*18];
            }
            c = sigf(gf)*c + sigf(gi)*tanhfast(gg);
            h = sigf(go)*tanhfast(c);
            // own chunk into smem for next step's fast path
            xh[us*512 + uul*16 + sq5] = h;
            // peer-visible hT store (must precede flag release)
            float* hw = (((ts & 1) ? hT_grp0 : hT_grp1)) + us*512 + uul*16 + sq5;
            *hw = h;
        }
        __syncthreads();
        if (tid == 0) {
            __threadfence();                 // leader-only fence (CG grid-sync pattern)
            *myflag = F0 + (unsigned)ts + 1u;
        }
        // fire-and-forget output store, outside the fence shadow
        g_hout[((sbase + sq5)*SS + tx)*512 + dir*256 + uu] = h;
    }
}

// ---------------- emissions + tag argmax ----------------
__global__ __launch_bounds__(256) void feats_kernel(const float* __restrict__ tagW,
                             const float* __restrict__ tagb, float* __restrict__ out)
{
    int w = blockIdx.x*8 + (threadIdx.x >> 5);
    int lane = threadIdx.x & 31;
    float xv[22];
    #pragma unroll
    for (int i = 0; i < 22; i++) {
        int j = lane + 32*i;
        float v;
        if (j < 512)      v = g_hout[w*512 + j];
        else if (j < 576) v = g_chvec[w*64 + (j-512)];
        else              v = g_fv[w*128 + (j-576)];
        xv[i] = v;
    }
    float best = -1e30f; int bestk = 0;
    for (int k = 0; k < KK; k++) {
        float acc = 0.f;
        const float* wr = tagW + k*704;
        #pragma unroll
        for (int i = 0; i < 22; i++) acc += wr[lane + 32*i]*xv[i];
        #pragma unroll
        for (int off = 16; off; off >>= 1) acc += __shfl_xor_sync(0xffffffffu, acc, off);
        acc += tagb[k];
        if (lane == 0) g_feats[w*KK + k] = acc;
        if (acc > best) { best = acc; bestk = k; }
    }
    if (lane == 0) out[BB + NW + w] = (float)bestk;
}

// ---------------- CRF Viterbi: smem backpointers + feats prefetch ----------------
__global__ void viterbi_kernel(const int* __restrict__ mask, const float* __restrict__ trans,
                               float* __restrict__ out)
{
    int b = blockIdx.x;
    int k = threadIdx.x;
    __shared__ float sc[32];
    __shared__ float tr[KK*KK];
    __shared__ int msk[SS];
    __shared__ short bp_sm[(SS-1)*KK];
    for (int i = k; i < KK*KK; i += 32) tr[i] = trans[i];
    for (int i = k; i < SS; i += 32) msk[i] = mask[b*SS + i];
    if (k < KK) sc[k] = g_feats[(b*SS + 0)*KK + k] + trans[NSTART*KK + k];
    __syncwarp();
    float ftn = (k < KK) ? g_feats[(b*SS + 1)*KK + k] : 0.f;
    for (int step = 1; step < SS; step++) {
        float ft = ftn;
        if (step + 1 < SS && k < KK) ftn = g_feats[(b*SS + step + 1)*KK + k];
        float best = -1e30f; int bp = 0;
        if (k < KK) {
            float bestA = -1e30f, bestB = -1e30f; int bpA = 0, bpB = 14;
            #pragma unroll
            for (int p = 0; p < 14; p++) {
                float v = sc[p] + tr[p*KK + k];
                if (v > bestA) { bestA = v; bpA = p; }
            }
            #pragma unroll
            for (int p = 14; p < KK; p++) {
                float v = sc[p] + tr[p*KK + k];
                if (v > bestB) { bestB = v; bpB = p; }
            }
            if (bestB > bestA) { best = bestB; bp = bpB; }
            else               { best = bestA; bp = bpA; }
            best += ft;
            if (msk[step] == 0) { best = sc[k]; bp = k; }
        }
        __syncwarp();
        if (k < KK) { sc[k] = best; bp_sm[(step-1)*KK + k] = (short)bp; }
        __syncwarp();
    }
    if (k == 0) {
        float best = -1e30f; int bt = 0;
        for (int p = 0; p < KK; p++) {
            float f = sc[p] + tr[p*KK + NSTOP];
            if (f > best) { best = f; bt = p; }
        }
        out[b] = best;
        int tag = bt;
        out[BB + b*SS + (SS-1)] = (float)tag;
        for (int step = SS-1; step >= 1; step--) {
            tag = bp_sm[(step-1)*KK + tag];
            out[BB + b*SS + (step-1)] = (float)tag;
        }
    }
}

// ---------------- launch ----------------
extern "C" void kernel_launch(void* const* d_in, const int* in_sizes, int n_in,
                              void* d_out, int out_size)
{
    (void)in_sizes; (void)n_in; (void)out_size;
    const int*   words2ix  = (const int*)  d_in[0];
    const int*   chars2ix  = (const int*)  d_in[1];
    const float* features  = (const float*)d_in[2];
    const int*   mask      = (const int*)  d_in[3];
    const float* word_emb  = (const float*)d_in[4];
    const float* char_emb  = (const float*)d_in[5];
    const float* cWih_f = (const float*)d_in[6];
    const float* cWhh_f = (const float*)d_in[7];
    const float* cbih_f = (const float*)d_in[8];
    const float* cbhh_f = (const float*)d_in[9];
    const float* cWih_b = (const float*)d_in[10];
    const float* cWhh_b = (const float*)d_in[11];
    const float* cbih_b = (const float*)d_in[12];
    const float* cbhh_b = (const float*)d_in[13];
    const float* coW    = (const float*)d_in[14];
    const float* cob    = (const float*)d_in[15];
    const float* featW  = (const float*)d_in[16];
    const float* featb  = (const float*)d_in[17];
    const float* lWih_f = (const float*)d_in[18];
    const float* lWhh_f = (const float*)d_in[19];
    const float* lbih_f = (const float*)d_in[20];
    const float* lbhh_f = (const float*)d_in[21];
    const float* lWih_b = (const float*)d_in[22];
    const float* lWhh_b = (const float*)d_in[23];
    const float* lbih_b = (const float*)d_in[24];
    const float* lbhh_b = (const float*)d_in[25];
    const float* tagW   = (const float*)d_in[26];
    const float* tagb   = (const float*)d_in[27];
    const float* trans  = (const float*)d_in[28];
    float* out = (float*)d_out;

    prep_transpose_kernel<<<64, 256>>>(coW, cWih_f, cWih_b);
    ce_proj_kernel<<<dim3(CV,2), 256>>>(char_emb, cbih_f, cbhh_f, cbih_b, cbhh_b);
    w4_kernel<<<dim3(4,2), 256>>>(lWih_f, lWih_b, featW, featb,
                                  lbih_f, lbhh_f, lbih_b, lbhh_b);
    char_lstm_kernel<<<dim3(512,2), 256>>>(chars2ix, cWhh_f, cWhh_b);
    chvec_kernel<<<512, 256>>>(cob);
    fv_vec_kernel<<<512, 256>>>(features, featW, featb, words2ix, word_emb);
    gx_gemm_kernel<<<dim3(16,128), 256>>>(lWih_f, lWih_b, features);
    lstm_persist_kernel<<<128, 512>>>(lWhh_f, lWhh_b);
    feats_kernel<<<NW/8, 256>>>(tagW, tagb, out);
    viterbi_kernel<<<BB, 32>>>(mask, trans, out);
}

// round 16
// speedup vs baseline: 1.0385x; 1.0385x over previous
#include <cuda_runtime.h>
#include <math.h>

#define BB 128
#define SS 128
#define WW 16
#define CEd 64
#define HHd 256
#define KK 27
#define NSTART 25
#define NSTOP 26
#define NW (BB*SS)
#define CV 500

typedef unsigned long long u64;

__device__ __forceinline__ u64 pack2(float a, float b){ u64 r; asm("mov.b64 %0,{%1,%2};":"=l"(r):"f"(a),"f"(b)); return r; }
__device__ __forceinline__ float2 unpack2(u64 v){ float2 f; asm("mov.b64 {%0,%1},%2;":"=f"(f.x),"=f"(f.y):"l"(v)); return f; }
__device__ __forceinline__ u64 ffma2(u64 a, u64 b, u64 c){ u64 d; asm("fma.rn.f32x2 %0,%1,%2,%3;":"=l"(d):"l"(a),"l"(b),"l"(c)); return d; }
__device__ __forceinline__ u64 add2(u64 a, u64 b){ u64 d; asm("add.rn.f32x2 %0,%1,%2;":"=l"(d):"l"(a),"l"(b)); return d; }

__device__ __forceinline__ float sigf(float x){ return 1.0f/(1.0f+__expf(-x)); }
__device__ __forceinline__ float tanhfast(float x){ return 2.0f/(1.0f+__expf(-2.0f*x)) - 1.0f; }

// ---------------- static scratch ----------------
__device__ float g_coWT[128*64];
__device__ float g_cWT[2*64*256];
__device__ float g_cproj[2*CV*256];
__device__ float g_hf[NW*CEd];
__device__ float g_hb[NW*CEd];
__device__ float g_chvec[NW*CEd];
__device__ float g_fv[NW*128];
__device__ float g_vec192[NW*192];
__device__ float g_W4[2*1024*4];
__device__ float g_bias2[2*1024];
__device__ float g_gx[2*SS*BB*1024];
__device__ float g_hT[2*2*8*4096];             // [buf][dir][sg][256u][16s]
__device__ float g_hout[NW*512];
__device__ float g_feats[NW*KK];
__device__ volatile unsigned g_flag[16*16*8];  // [grp][ub] stride 8, monotonic

// ---------------- tiny transposes ----------------
__global__ void prep_transpose_kernel(const float* __restrict__ coW,
    const float* __restrict__ cWf, const float* __restrict__ cWb)
{
    int i = blockIdx.x*256 + threadIdx.x;
    if (i < 64*128) {
        int m = i >> 7, j = i & 127;
        g_coWT[j*64 + m] = coW[i];
    }
    if (i < 256*64) {
        int t = i >> 6, j = i & 63;
        g_cWT[0*16384 + j*256 + t] = cWf[i];
        g_cWT[1*16384 + j*256 + t] = cWb[i];
    }
}

// ---------------- fold char_emb @ Wih^T + bias into vocab table ----------------
__global__ void ce_proj_kernel(const float* __restrict__ ce,
    const float* __restrict__ bihf, const float* __restrict__ bhhf,
    const float* __restrict__ bihb, const float* __restrict__ bhhb)
{
    int v = blockIdx.x, dir = blockIdx.y, t = threadIdx.x;
    __shared__ float e[64];
    if (t < 64) e[t] = ce[v*64 + t];
    __syncthreads();
    const float* WT = g_cWT + dir*16384;
    float acc = dir ? (bihb[t] + bhhb[t]) : (bihf[t] + bhhf[t]);
    #pragma unroll
    for (int j = 0; j < 64; j++) acc += WT[j*256 + t]*e[j];
    g_cproj[(dir*CV + v)*256 + t] = acc;
}

// ---------------- fold Wih_fv @ featW (rank-4) + bias ----------------
__global__ void w4_kernel(const float* __restrict__ Wf, const float* __restrict__ Wb,
    const float* __restrict__ featW, const float* __restrict__ featb,
    const float* __restrict__ bihf, const float* __restrict__ bhhf,
    const float* __restrict__ bihb, const float* __restrict__ bhhb)
{
    int r = blockIdx.x*256 + threadIdx.x;
    int dir = blockIdx.y;
    const float* W = dir ? Wb : Wf;
    float a0=0.f,a1=0.f,a2=0.f,a3=0.f,ab=0.f;
    #pragma unroll 4
    for (int m = 0; m < 128; m++) {
        float w = W[r*320 + 192 + m];
        a0 += w*featW[m*4+0]; a1 += w*featW[m*4+1];
        a2 += w*featW[m*4+2]; a3 += w*featW[m*4+3];
        ab += w*featb[m];
    }
    g_W4[(dir*1024+r)*4+0]=a0; g_W4[(dir*1024+r)*4+1]=a1;
    g_W4[(dir*1024+r)*4+2]=a2; g_W4[(dir*1024+r)*4+3]=a3;
    g_bias2[dir*1024+r] = (dir ? bihb[r]+bhhb[r] : bihf[r]+bhhf[r]) + ab;
}

// ---------------- char BiLSTM: two-group software pipeline ----------------
__global__ __launch_bounds__(256,2) void char_lstm_kernel(
    const int* __restrict__ chars2ix,
    const float* __restrict__ Whh_f, const float* __restrict__ Whh_b)
{
    int t = threadIdx.x;
    int dir = blockIdx.y;
    const float* Whh = dir ? Whh_b : Whh_f;
    float* hout = dir ? g_hb : g_hf;
    const float* tab = g_cproj + dir*CV*256;

    u64 whp[32];
    #pragma unroll
    for (int j = 0; j < 32; j++) whp[j] = *(const u64*)&Whh[t*64 + 2*j];

    __shared__ __align__(16) float hs[2][8*68];
    __shared__ float cs[2][512];
    __shared__ float gs[2][256*9];
    __shared__ int cix[256];

    for (int q = blockIdx.x; q < NW/16; q += gridDim.x) {
        int w0 = q*16;
        cix[t] = chars2ix[w0*WW + t];
        for (int i = t; i < 1088; i += 256) ((float*)hs)[i] = 0.f;
        cs[0][t] = 0.f; cs[0][t+256] = 0.f;
        cs[1][t] = 0.f; cs[1][t+256] = 0.f;
        __syncthreads();

        #pragma unroll 1
        for (int p = 0; p <= 32; p++) {
            if (p >= 1) {
                int gu = (p-1) & 1;
                #pragma unroll
                for (int rep = 0; rep < 2; rep++) {
                    int idx = t + rep*256;
                    int u = idx >> 3, w = idx & 7;
                    float gi = gs[gu][u*9 + w];
                    float gf = gs[gu][(64+u)*9 + w];
                    float gg = gs[gu][(128+u)*9 + w];
                    float go = gs[gu][(192+u)*9 + w];
                    float c = sigf(gf)*cs[gu][idx] + sigf(gi)*tanhfast(gg);
                    cs[gu][idx] = c;
                    hs[gu][w*68 + u] = sigf(go)*tanhfast(c);
                }
            }
            if (p < 32) {
                int gm = p & 1, sm = p >> 1;
                int st = dir ? (WW-1-sm) : sm;
                float gxv[8];
                #pragma unroll
                for (int w = 0; w < 8; w++)
                    gxv[w] = tab[cix[(gm*8 + w)*16 + st]*256 + t];
                u64 acc[8];
                #pragma unroll
                for (int w = 0; w < 8; w++) acc[w] = 0ull;
                #pragma unroll
                for (int j4 = 0; j4 < 16; j4++) {
                    #pragma unroll
                    for (int w = 0; w < 8; w++) {
                        ulonglong2 hv = *(const ulonglong2*)&hs[gm][w*68 + j4*4];
                        acc[w] = ffma2(whp[2*j4],   hv.x, acc[w]);
                        acc[w] = ffma2(whp[2*j4+1], hv.y, acc[w]);
                    }
                }
                #pragma unroll
                for (int w = 0; w < 8; w++) {
                    float2 f = unpack2(acc[w]);
                    gs[gm][t*9 + w] = f.x + f.y + gxv[w];
                }
            }
            __syncthreads();
        }
        #pragma unroll
        for (int rep = 0; rep < 4; rep++) {
            int idx = t + rep*256;
            int u = idx & 63, wl = idx >> 6;
            hout[(w0 + wl)*CEd + u] = hs[wl >> 3][(wl & 7)*68 + u];
        }
        __syncthreads();
    }
}

// ---------------- chvec ----------------
__global__ __launch_bounds__(256) void chvec_kernel(const float* __restrict__ cob)
{
    for (int i = blockIdx.x*blockDim.x + threadIdx.x; i < NW*CEd; i += gridDim.x*blockDim.x) {
        int w = i >> 6, m = i & 63;
        float acc = cob[m];
        const float* hf = g_hf + w*CEd;
        const float* hb = g_hb + w*CEd;
        #pragma unroll 8
        for (int j = 0; j < 64; j++) acc += g_coWT[j*64 + m]*hf[j];
        #pragma unroll 8
        for (int j = 0; j < 64; j++) acc += g_coWT[(64+j)*64 + m]*hb[j];
        g_chvec[i] = acc;
    }
}

// ---------------- fv + assemble vec192 ----------------
__global__ void fv_vec_kernel(const float* __restrict__ features,
                              const float* __restrict__ featW, const float* __restrict__ featb,
                              const int* __restrict__ words2ix, const float* __restrict__ word_emb)
{
    for (int idx = blockIdx.x*blockDim.x + threadIdx.x; idx < NW*320; idx += gridDim.x*blockDim.x) {
        int w = idx / 320;
        int j = idx - w*320;
        if (j < 128) {
            g_vec192[w*192 + j] = word_emb[ words2ix[w]*128 + j ];
        } else if (j < 192) {
            g_vec192[w*192 + j] = g_chvec[w*64 + (j-128)];
        } else {
            int m = j - 192;
            int b = w >> 7, s = w & 127;
            float v = featb[m];
            #pragma unroll
            for (int f = 0; f < 4; f++) v += featW[m*4+f]*features[(b*4+f)*SS + s];
            g_fv[w*128 + m] = v;
        }
    }
}

// ---------------- input GEMM (K=192), register-prefetch pipelined ----------------
__global__ __launch_bounds__(256,2) void gx_gemm_kernel(
    const float* __restrict__ Wf, const float* __restrict__ Wb,
    const float* __restrict__ features)
{
    int ntile = blockIdx.x, mtile = blockIdx.y;
    int dir = ntile >> 3;
    const float* W = dir ? Wb : Wf;
    int n0 = (ntile & 7) * 128, m0 = mtile * 128;

    __shared__ float As[8][132];
    __shared__ float Bs[8][132];

    int tid = threadIdx.x;
    int lrow = tid >> 1, lk = (tid & 1) * 4;
    int m = m0 + lrow, tt = m >> 7, sq = m & 127;
    const float* arow = g_vec192 + (sq*SS + tt)*192;
    const float* brow = W + (n0 + lrow)*320;
    int tm = tid >> 4, tn = tid & 15;

    u64 acc[8][4];
    #pragma unroll
    for (int i=0;i<8;i++){ acc[i][0]=0ull; acc[i][1]=0ull; acc[i][2]=0ull; acc[i][3]=0ull; }

    float4 av = *(const float4*)(arow + lk);
    float4 bv = *(const float4*)(brow + lk);

    for (int kb = 0; kb < 192; kb += 8) {
        __syncthreads();
        As[lk+0][lrow]=av.x; As[lk+1][lrow]=av.y; As[lk+2][lrow]=av.z; As[lk+3][lrow]=av.w;
        Bs[lk+0][lrow]=bv.x; Bs[lk+1][lrow]=bv.y; Bs[lk+2][lrow]=bv.z; Bs[lk+3][lrow]=bv.w;
        if (kb + 8 < 192) {
            av = *(const float4*)(arow + kb + 8 + lk);
            bv = *(const float4*)(brow + kb + 8 + lk);
        }
        __syncthreads();
        #pragma unroll
        for (int k=0;k<8;k++){
            float af[8];
            *(float4*)(af)   = *(const float4*)&As[k][tm*8];
            *(float4*)(af+4) = *(const float4*)&As[k][tm*8+4];
            ulonglong2 b0 = *(const ulonglong2*)&Bs[k][tn*8];
            ulonglong2 b1 = *(const ulonglong2*)&Bs[k][tn*8+4];
            #pragma unroll
            for (int i=0;i<8;i++){
                u64 ap = pack2(af[i], af[i]);
                acc[i][0]=ffma2(ap,b0.x,acc[i][0]);
                acc[i][1]=ffma2(ap,b0.y,acc[i][1]);
                acc[i][2]=ffma2(ap,b1.x,acc[i][2]);
                acc[i][3]=ffma2(ap,b1.y,acc[i][3]);
            }
        }
    }
    float w4v[8][4], bv2[8];
    #pragma unroll
    for (int j=0;j<8;j++){
        int r = n0 + tn*8 + j;
        *(float4*)&w4v[j][0] = *(const float4*)&g_W4[(dir*1024+r)*4];
        bv2[j] = g_bias2[dir*1024+r];
    }
    #pragma unroll
    for (int i=0;i<8;i++){
        int mm = m0 + tm*8 + i;
        int tq = mm >> 7, s = mm & 127;
        float f0 = features[(s*4+0)*SS + tq];
        float f1 = features[(s*4+1)*SS + tq];
        float f2 = features[(s*4+2)*SS + tq];
        float f3 = features[(s*4+3)*SS + tq];
        float* dst = g_gx + ((dir*SS + tq)*BB + s)*1024 + n0 + tn*8;
        float o[8];
        #pragma unroll
        for (int j2=0;j2<4;j2++){
            float2 f = unpack2(acc[i][j2]);
            o[2*j2]   = f.x;
            o[2*j2+1] = f.y;
        }
        #pragma unroll
        for (int j=0;j<8;j++)
            o[j] += bv2[j] + f0*w4v[j][0] + f1*w4v[j][1] + f2*w4v[j][2] + f3*w4v[j][3];
        *(float4*)(dst)   = *(float4*)(o);
        *(float4*)(dst+4) = *(float4*)(o+4);
    }
}

// ---------------- persistent recurrent BiLSTM: 256 blocks (2/SM), 16-unit slices ----------------
// block bx: grp = bx & 15 (dir = grp>>3, sg = grp&7), ub = bx>>4 (0..15, 16 units each).
// matvec role: kq = tid>>6 (warp-pair uniform), r = tid&63 (row: gate g=r>>4, unit r&15).
// kq group consumes chunks kq*4..kq*4+3 (each chunk = one producer block's 256 h floats).
__global__ __launch_bounds__(256,2) void lstm_persist_kernel(
    const float* __restrict__ Whh_f, const float* __restrict__ Whh_b)
{
    int bx = blockIdx.x, tid = threadIdx.x;
    int grp = bx & 15, ub = bx >> 4;
    int dir = grp >> 3, sg = grp & 7, sbase = sg*16;
    const float* Whh = dir ? Whh_b : Whh_f;

    const int kq = tid >> 6;
    const int r  = tid & 63;
    const int uul = tid & 15, sq = tid >> 4;     // update role: unit-in-block, seq
    const int gxcol = ub*16 + uul;               // gx column base (unit)

    float w[64];
    {
        int g = r >> 4, u = ub*16 + (r & 15);
        #pragma unroll
        for (int k = 0; k < 64; k++) w[k] = Whh[(g*HHd + u)*HHd + kq*64 + k];
    }

    __shared__ __align__(16) float xh[4096];       // [global unit][seq]
    __shared__ float gsm[4*64*18];                 // [kq][row 64][pitch 18]

    float* hT_grp0 = g_hT + ((0*2 + dir)*8 + sg)*4096;
    float* hT_grp1 = g_hT + ((1*2 + dir)*8 + sg)*4096;
    volatile unsigned* myflag = &g_flag[(grp*16 + ub)*8];
    const unsigned F0 = *myflag;

    float c = 0.f;

    #pragma unroll 1
    for (int ts = 0; ts < SS; ts++) {
        int tx = dir ? (SS-1-ts) : ts;
        float gxv0, gxv1, gxv2, gxv3;
        {
            const float* gp = g_gx + ((dir*SS + tx)*BB + sbase + sq)*1024 + gxcol;
            gxv0 = __ldcg(gp);
            gxv1 = __ldcg(gp + 256);
            gxv2 = __ldcg(gp + 512);
            gxv3 = __ldcg(gp + 768);
        }
        u64 acc[8];
        #pragma unroll
        for (int j = 0; j < 8; j++) acc[j] = 0ull;
        #pragma unroll
        for (int ci = 0; ci < 4; ci++) {
            int ch = kq*4 + ci;
            bool own_fast = (ch == ub) && (ts > 0);   // group-uniform
            if (!own_fast) {
                if (ts > 0) {
                    volatile unsigned* fl = &g_flag[(grp*16 + ch)*8];
                    unsigned tgt = F0 + (unsigned)ts;
                    while (*fl < tgt) { }
                }
                {
                    float4 hv;
                    if (ts == 0) hv = make_float4(0.f,0.f,0.f,0.f);
                    else {
                        const float* src = (((ts & 1) ? hT_grp1 : hT_grp0)) + ch*256 + r*4;
                        hv = __ldcg((const float4*)src);
                    }
                    *(float4*)&xh[ch*256 + r*4] = hv;
                }
                asm volatile("bar.sync %0, %1;" :: "r"(kq+1), "r"(64) : "memory");
            }
            const float* xb = xh + ch*256;
            int woff = ci*16;
            #pragma unroll
            for (int k = 0; k < 16; k++) {
                u64 wp = pack2(w[woff+k], w[woff+k]);
                const float* xr = xb + k*16;
                ulonglong2 x0 = *(const ulonglong2*)(xr);
                ulonglong2 x1 = *(const ulonglong2*)(xr+4);
                acc[0]=ffma2(wp,x0.x,acc[0]); acc[1]=ffma2(wp,x0.y,acc[1]);
                acc[2]=ffma2(wp,x1.x,acc[2]); acc[3]=ffma2(wp,x1.y,acc[3]);
                ulonglong2 x2 = *(const ulonglong2*)(xr+8);
                ulonglong2 x3 = *(const ulonglong2*)(xr+12);
                acc[4]=ffma2(wp,x2.x,acc[4]); acc[5]=ffma2(wp,x2.y,acc[5]);
                acc[6]=ffma2(wp,x3.x,acc[6]); acc[7]=ffma2(wp,x3.y,acc[7]);
            }
        }
        {
            float* gp = &gsm[(kq*64 + r)*18];
            #pragma unroll
            for (int j = 0; j < 8; j++) *(u64*)&gp[2*j] = acc[j];
        }
        __syncthreads();
        float h;
        {
            float gi = gxv0, gf = gxv1, gg = gxv2, go = gxv3;
            #pragma unroll
            for (int q = 0; q < 4; q++) {
                const float* gp = &gsm[q*64*18 + sq];
                gi += gp[(uul)*18];
                gf += gp[(16+uul)*18];
                gg += gp[(32+uul)*18];
                go += gp[(48+uul)*18];
            }
            c = sigf(gf)*c + sigf(gi)*tanhfast(gg);
            h = sigf(go)*tanhfast(c);
            xh[(ub*16 + uul)*16 + sq] = h;           // own chunk for next step fast path
            float* hw = (((ts & 1) ? hT_grp0 : hT_grp1)) + ub*256 + uul*16 + sq;
            *hw = h;
        }
        __syncthreads();
        if (tid == 0) {
            __threadfence();
            *myflag = F0 + (unsigned)ts + 1u;
        }
        g_hout[((sbase + sq)*SS + tx)*512 + dir*256 + gxcol] = h;
    }
}

// ---------------- emissions + tag argmax ----------------
__global__ __launch_bounds__(256) void feats_kernel(const float* __restrict__ tagW,
                             const float* __restrict__ tagb, float* __restrict__ out)
{
    int w = blockIdx.x*8 + (threadIdx.x >> 5);
    int lane = threadIdx.x & 31;
    float xv[22];
    #pragma unroll
    for (int i = 0; i < 22; i++) {
        int j = lane + 32*i;
        float v;
        if (j < 512)      v = g_hout[w*512 + j];
        else if (j < 576) v = g_chvec[w*64 + (j-512)];
        else              v = g_fv[w*128 + (j-576)];
        xv[i] = v;
    }
    float best = -1e30f; int bestk = 0;
    for (int k = 0; k < KK; k++) {
        float acc = 0.f;
        const float* wr = tagW + k*704;
        #pragma unroll
        for (int i = 0; i < 22; i++) acc += wr[lane + 32*i]*xv[i];
        #pragma unroll
        for (int off = 16; off; off >>= 1) acc += __shfl_xor_sync(0xffffffffu, acc, off);
        acc += tagb[k];
        if (lane == 0) g_feats[w*KK + k] = acc;
        if (acc > best) { best = acc; bestk = k; }
    }
    if (lane == 0) out[BB + NW + w] = (float)bestk;
}

// ---------------- CRF Viterbi: smem backpointers + feats prefetch ----------------
__global__ void viterbi_kernel(const int* __restrict__ mask, const float* __restrict__ trans,
                               float* __restrict__ out)
{
    int b = blockIdx.x;
    int k = threadIdx.x;
    __shared__ float sc[32];
    __shared__ float tr[KK*KK];
    __shared__ int msk[SS];
    __shared__ short bp_sm[(SS-1)*KK];
    for (int i = k; i < KK*KK; i += 32) tr[i] = trans[i];
    for (int i = k; i < SS; i += 32) msk[i] = mask[b*SS + i];
    if (k < KK) sc[k] = g_feats[(b*SS + 0)*KK + k] + trans[NSTART*KK + k];
    __syncwarp();
    float ftn = (k < KK) ? g_feats[(b*SS + 1)*KK + k] : 0.f;
    for (int step = 1; step < SS; step++) {
        float ft = ftn;
        if (step + 1 < SS && k < KK) ftn = g_feats[(b*SS + step + 1)*KK + k];
        float best = -1e30f; int bp = 0;
        if (k < KK) {
            float bestA = -1e30f, bestB = -1e30f; int bpA = 0, bpB = 14;
            #pragma unroll
            for (int p = 0; p < 14; p++) {
                float v = sc[p] + tr[p*KK + k];
                if (v > bestA) { bestA = v; bpA = p; }
            }
            #pragma unroll
            for (int p = 14; p < KK; p++) {
                float v = sc[p] + tr[p*KK + k];
                if (v > bestB) { bestB = v; bpB = p; }
            }
            if (bestB > bestA) { best = bestB; bp = bpB; }
            else               { best = bestA; bp = bpA; }
            best += ft;
            if (msk[step] == 0) { best = sc[k]; bp = k; }
        }
        __syncwarp();
        if (k < KK) { sc[k] = best; bp_sm[(step-1)*KK + k] = (short)bp; }
        __syncwarp();
    }
    if (k == 0) {
        float best = -1e30f; int bt = 0;
        for (int p = 0; p < KK; p++) {
            float f = sc[p] + tr[p*KK + NSTOP];
            if (f > best) { best = f; bt = p; }
        }
        out[b] = best;
        int tag = bt;
        out[BB + b*SS + (SS-1)] = (float)tag;
        for (int step = SS-1; step >= 1; step--) {
            tag = bp_sm[(step-1)*KK + tag];
            out[BB + b*SS + (step-1)] = (float)tag;
        }
    }
}

// ---------------- launch ----------------
extern "C" void kernel_launch(void* const* d_in, const int* in_sizes, int n_in,
                              void* d_out, int out_size)
{
    (void)in_sizes; (void)n_in; (void)out_size;
    const int*   words2ix  = (const int*)  d_in[0];
    const int*   chars2ix  = (const int*)  d_in[1];
    const float* features  = (const float*)d_in[2];
    const int*   mask      = (const int*)  d_in[3];
    const float* word_emb  = (const float*)d_in[4];
    const float* char_emb  = (const float*)d_in[5];
    const float* cWih_f = (const float*)d_in[6];
    const float* cWhh_f = (const float*)d_in[7];
    const float* cbih_f = (const float*)d_in[8];
    const float* cbhh_f = (const float*)d_in[9];
    const float* cWih_b = (const float*)d_in[10];
    const float* cWhh_b = (const float*)d_in[11];
    const float* cbih_b = (const float*)d_in[12];
    const float* cbhh_b = (const float*)d_in[13];
    const float* coW    = (const float*)d_in[14];
    const float* cob    = (const float*)d_in[15];
    const float* featW  = (const float*)d_in[16];
    const float* featb  = (const float*)d_in[17];
    const float* lWih_f = (const float*)d_in[18];
    const float* lWhh_f = (const float*)d_in[19];
    const float* lbih_f = (const float*)d_in[20];
    const float* lbhh_f = (const float*)d_in[21];
    const float* lWih_b = (const float*)d_in[22];
    const float* lWhh_b = (const float*)d_in[23];
    const float* lbih_b = (const float*)d_in[24];
    const float* lbhh_b = (const float*)d_in[25];
    const float* tagW   = (const float*)d_in[26];
    const float* tagb   = (const float*)d_in[27];
    const float* trans  = (const float*)d_in[28];
    float* out = (float*)d_out;

    prep_transpose_kernel<<<64, 256>>>(coW, cWih_f, cWih_b);
    ce_proj_kernel<<<dim3(CV,2), 256>>>(char_emb, cbih_f, cbhh_f, cbih_b, cbhh_b);
    w4_kernel<<<dim3(4,2), 256>>>(lWih_f, lWih_b, featW, featb,
                                  lbih_f, lbhh_f, lbih_b, lbhh_b);
    char_lstm_kernel<<<dim3(512,2), 256>>>(chars2ix, cWhh_f, cWhh_b);
    chvec_kernel<<<512, 256>>>(cob);
    fv_vec_kernel<<<512, 256>>>(features, featW, featb, words2ix, word_emb);
    gx_gemm_kernel<<<dim3(16,128), 256>>>(lWih_f, lWih_b, features);
    lstm_persist_kernel<<<256, 256>>>(lWhh_f, lWhh_b);
    feats_kernel<<<NW/8, 256>>>(tagW, tagb, out);
    viterbi_kernel<<<BB, 32>>>(mask, trans, out);
}